// round 13
// baseline (speedup 1.0000x reference)
#include <cuda_runtime.h>
#include <cuda_bf16.h>
#include <cuda_fp16.h>
#include <stdint.h>

#define BATCH 8
#define SEQ1  2048
#define SEQ2  2048
#define DIM   1024
#define PGRID 304   // persistent CTAs: 2 per SM x 152 SMs

using bf16 = __nv_bfloat16;

// ---------------- scratch (static __device__, zero-init, no allocation) -----
__device__ int    g_idx[BATCH * SEQ1];
__device__ int    g_nb[BATCH];
__device__ bf16   g_in1h[(size_t)BATCH*SEQ1*DIM];
__device__ bf16   g_in1l[(size_t)BATCH*SEQ1*DIM];
__device__ bf16   g_in2h[(size_t)BATCH*SEQ2*DIM];
__device__ bf16   g_in2l[(size_t)BATCH*SEQ2*DIM];
__device__ bf16   g_wh[(size_t)DIM*DIM];
__device__ bf16   g_wl[(size_t)DIM*DIM];
__device__ bf16   g_o1h[(size_t)BATCH*SEQ1*DIM];
__device__ bf16   g_o1l[(size_t)BATCH*SEQ1*DIM];
__device__ __half g_t1f[(size_t)BATCH*DIM*SEQ1];
__device__ float  g_scores[(size_t)BATCH*SEQ2*SEQ1];
__device__ __half g_pf[(size_t)BATCH*SEQ2*SEQ1];

__device__ __forceinline__ void split2(float x, bf16 &h, bf16 &l) {
    h = __float2bfloat16(x);
    l = __float2bfloat16(x - __bfloat162float(h));
}

// ---------------- mask compaction ----------------
__global__ __launch_bounds__(256)
void build_idx(const unsigned* __restrict__ mask, int* __restrict__ idx,
               int* __restrict__ nb)
{
    const int b = blockIdx.x, tid = threadIdx.x;
    const int lane = tid & 31, wid = tid >> 5;
    const unsigned* mk = mask + (size_t)b * SEQ1;
    __shared__ int wsum[8];

    int bits[8], c = 0;
#pragma unroll
    for (int k = 0; k < 8; k++) {
        bits[k] = (mk[tid * 8 + k] != 0u) ? 1 : 0;
        c += bits[k];
    }
    int pre = c;
#pragma unroll
    for (int o = 1; o < 32; o <<= 1) {
        int n = __shfl_up_sync(0xffffffffu, pre, o);
        if (lane >= o) pre += n;
    }
    if (lane == 31) wsum[wid] = pre;
    __syncthreads();
    int woff = 0;
    for (int w = 0; w < wid; w++) woff += wsum[w];
    int pos = woff + pre - c;
#pragma unroll
    for (int k = 0; k < 8; k++)
        if (bits[k]) idx[b * SEQ1 + pos++] = tid * 8 + k;
    if (tid == 255) nb[b] = woff + pre;
}

// ---------------- split (fp32 -> hi/lo bf16) ----------------
__global__ __launch_bounds__(256) void split_kernel(const float* __restrict__ x,
                                                    bf16* __restrict__ h,
                                                    bf16* __restrict__ l) {
    size_t i = ((size_t)blockIdx.x * 256 + threadIdx.x) * 4;
    float4 v = *(const float4*)(x + i);
    bf16 h0,h1,h2,h3,l0,l1,l2,l3;
    split2(v.x,h0,l0); split2(v.y,h1,l1); split2(v.z,h2,l2); split2(v.w,h3,l3);
    __nv_bfloat162 a, b;
    a.x=h0; a.y=h1; b.x=h2; b.y=h3;
    ((__nv_bfloat162*)(h+i))[0] = a; ((__nv_bfloat162*)(h+i))[1] = b;
    a.x=l0; a.y=l1; b.x=l2; b.y=l3;
    ((__nv_bfloat162*)(l+i))[0] = a; ((__nv_bfloat162*)(l+i))[1] = b;
}

// ---------------- gather + split + transpose of input1 (compacted) ----------
__global__ __launch_bounds__(256)
void gather_split(const float* __restrict__ x, const int* __restrict__ idxp,
                  const int* __restrict__ nbp,
                  bf16* __restrict__ ch, bf16* __restrict__ cl,
                  __half* __restrict__ tf)
{
    const int b  = blockIdx.z;
    const int j0 = blockIdx.x * 32, d0 = blockIdx.y * 32;
    const int nb = nbp[b];
    const int npad = (nb + 127) & ~127;
    if (j0 >= npad) return;

    const int tx = threadIdx.x & 31, ty = threadIdx.x >> 5;
    __shared__ float t[32][33];
    __shared__ int rows[32];
    if (threadIdx.x < 32)
        rows[threadIdx.x] =
            (j0 + threadIdx.x < nb) ? idxp[b * SEQ1 + j0 + threadIdx.x] : -1;
    __syncthreads();
#pragma unroll
    for (int k = 0; k < 4; k++) {
        const int j = ty + 8 * k;
        const int s = rows[j];
        t[j][tx] = (s >= 0) ? x[((size_t)b * SEQ1 + s) * DIM + d0 + tx] : 0.0f;
    }
    __syncthreads();
#pragma unroll
    for (int k = 0; k < 4; k++) {
        const int j = ty + 8 * k;
        bf16 h, l; split2(t[j][tx], h, l);
        const size_t o = ((size_t)b * SEQ1 + j0 + j) * DIM + d0 + tx;
        ch[o] = h; cl[o] = l;
    }
#pragma unroll
    for (int k = 0; k < 4; k++) {
        const size_t o = ((size_t)b * DIM + d0 + ty + 8 * k) * SEQ1 + j0 + tx;
        tf[o] = __float2half(t[tx][ty + 8 * k]);
    }
}

// ---------------- PTX helpers ----------------
#define CP16(dst, src) asm volatile("cp.async.cg.shared.global [%0], [%1], 16;\n" :: "r"(dst), "l"(src))
#define CP_COMMIT()    asm volatile("cp.async.commit_group;\n")
#define CP_WAIT2()     asm volatile("cp.async.wait_group 2;\n")
#define CP_WAIT1()     asm volatile("cp.async.wait_group 1;\n")
#define CP_WAIT0()     asm volatile("cp.async.wait_group 0;\n")

#define MMA_BF16(d, a, b) asm volatile( \
  "mma.sync.aligned.m16n8k16.row.col.f32.bf16.bf16.f32 " \
  "{%0,%1,%2,%3},{%4,%5,%6,%7},{%8,%9},{%0,%1,%2,%3};\n" \
  : "+f"(d[0]), "+f"(d[1]), "+f"(d[2]), "+f"(d[3]) \
  : "r"(a[0]), "r"(a[1]), "r"(a[2]), "r"(a[3]), "r"(b[0]), "r"(b[1]))

#define MMA_F16(d, a, b) asm volatile( \
  "mma.sync.aligned.m16n8k16.row.col.f32.f16.f16.f32 " \
  "{%0,%1,%2,%3},{%4,%5,%6,%7},{%8,%9},{%0,%1,%2,%3};\n" \
  : "+f"(d[0]), "+f"(d[1]), "+f"(d[2]), "+f"(d[3]) \
  : "r"(a[0]), "r"(a[1]), "r"(a[2]), "r"(a[3]), "r"(b[0]), "r"(b[1]))

#define LDSM_X4(r0, r1, r2, r3, addr) asm volatile( \
  "ldmatrix.sync.aligned.m8n8.x4.shared.b16 {%0,%1,%2,%3}, [%4];\n" \
  : "=r"(r0), "=r"(r1), "=r"(r2), "=r"(r3) : "r"(addr))

// ---------------------------------------------------------------------------
// Persistent HMMA NT GEMM: C = A*B^T. Fixed grid of PGRID CTAs; each CTA
// strides a flattened (tilesX x tilesY x BATCH) tile space, skipping dead
// (compacted-out) tiles. Per tile: block 128x128, BK=16, 128 threads = 4
// warps in 2x2 (warp tile 64x64), 4-stage cp.async, ldmatrix.x4 fragments.
//   PROD=3: split-bf16 3-product.  PROD=1: fp16 single product.
//   EPI=0: fp32 out.  EPI=2: split-bf16 out.
//   BND=1: skip m0 >= pad128(nb).  BND=2: skip n0 >= pad128(nb).
//   BND=3: K = pad16(nb).   Ks = row stride of A/B.
// ---------------------------------------------------------------------------
template<int EPI, int BND, int PROD>
__global__ __launch_bounds__(128, 2)
void gemm_mma(const bf16* __restrict__ Ahg, const bf16* __restrict__ Alg,
              const bf16* __restrict__ Bhg, const bf16* __restrict__ Blg,
              float* __restrict__ Cfg, bf16* __restrict__ Chg, bf16* __restrict__ Clg,
              const int* __restrict__ nbp,
              int N, int K, int Ks,
              size_t sA, size_t sB, size_t sC,
              int tilesX, int tilesY, int nTiles)
{
    extern __shared__ __align__(16) char dsm[];
    const uint32_t smem0 = (uint32_t)__cvta_generic_to_shared(dsm);
    constexpr uint32_t ARR = 6144u;                       // 128 x 24 halves x 2B
    constexpr uint32_t BOFF  = (PROD == 3) ? 2u * ARR : ARR;
    constexpr uint32_t STAGE = (PROD == 3) ? 4u * ARR : 2u * ARR;

    const int tid  = threadIdx.x;
    const int warp = tid >> 5, lane = tid & 31;
    const int wm = warp >> 1, wn = warp & 1;     // 2 x 2 grid -> 64x64 tiles
    const int g  = lane >> 2, tq = lane & 3;

    const uint32_t aOff =
        (uint32_t)(((lane & 15) * 24 + ((lane >> 4) & 1) * 8) * 2);
    const uint32_t bOffL =
        (uint32_t)((((lane & 7) + ((lane >> 4) & 1) * 8) * 24 +
                    ((lane >> 3) & 1) * 8) * 2);

    for (int t = blockIdx.x; t < nTiles; t += gridDim.x) {
        const int bx = t % tilesX;
        const int rem = t / tilesX;
        const int by = rem % tilesY;
        const int bz = rem / tilesY;
        const int m0 = by * 128, n0 = bx * 128;

        int Klogic = K;
        {
            const int nb = nbp[bz];
            const int npad = (nb + 127) & ~127;
            if (BND == 1 && m0 >= npad) continue;
            if (BND == 2 && n0 >= npad) continue;
            if (BND == 3) Klogic = (nb + 15) & ~15;
        }

        const bf16* Ah = Ahg + (size_t)bz * sA + (size_t)m0 * Ks;
        const bf16* Al = (PROD == 3) ? Alg + (size_t)bz * sA + (size_t)m0 * Ks : nullptr;
        const bf16* Bh = Bhg + (size_t)bz * sB + (size_t)n0 * Ks;
        const bf16* Bl = (PROD == 3) ? Blg + (size_t)bz * sB + (size_t)n0 * Ks : nullptr;

        float acc[4][8][4];
#pragma unroll
        for (int mt = 0; mt < 4; mt++)
#pragma unroll
            for (int nt = 0; nt < 8; nt++)
#pragma unroll
                for (int c = 0; c < 4; c++) acc[mt][nt][c] = 0.0f;

        const int NC = Klogic >> 4;
        if (NC <= 0) continue;

        auto issue = [&](int stg, int kk) {
            const uint32_t sb_ = smem0 + (uint32_t)stg * STAGE;
#pragma unroll
            for (int it = 0; it < 2; it++) {
                const int idx = it * 128 + tid;
                const int r = idx >> 1, u = idx & 1;
                const uint32_t off = (uint32_t)(r * 48 + u * 16);
                const size_t go = (size_t)r * Ks + kk + u * 8;
                CP16(sb_ + off, Ah + go);
                if (PROD == 3) CP16(sb_ + ARR + off, Al + go);
                CP16(sb_ + BOFF + off, Bh + go);
                if (PROD == 3) CP16(sb_ + 3u * ARR + off, Bl + go);
            }
            CP_COMMIT();
        };

        issue(0, 0);
        if (NC > 1) issue(1, 16);
        if (NC > 2) issue(2, 32);

        for (int i = 0; i < NC; i++) {
            if (i + 2 < NC)      { CP_WAIT2(); }
            else if (i + 1 < NC) { CP_WAIT1(); }
            else                 { CP_WAIT0(); }
            __syncthreads();
            if (i + 3 < NC) issue((i + 3) & 3, (i + 3) << 4);

            const uint32_t stb = smem0 + (uint32_t)(i & 3) * STAGE;

            uint32_t bh4[4][4];
#pragma unroll
            for (int p = 0; p < 4; p++) {
                const uint32_t bo =
                    stb + BOFF + (uint32_t)((wn * 64 + p * 16) * 48) + bOffL;
                LDSM_X4(bh4[p][0], bh4[p][1], bh4[p][2], bh4[p][3], bo);
            }
            uint32_t ah[4][4];
#pragma unroll
            for (int mt = 0; mt < 4; mt++) {
                const uint32_t ao =
                    stb + (uint32_t)((wm * 64 + mt * 16) * 48) + aOff;
                LDSM_X4(ah[mt][0], ah[mt][1], ah[mt][2], ah[mt][3], ao);
            }

            // phase 1: Ah*Bh
#pragma unroll
            for (int mt = 0; mt < 4; mt++)
#pragma unroll
                for (int nt = 0; nt < 8; nt++) {
                    if (PROD == 3) {
                        MMA_BF16(acc[mt][nt], ah[mt], (&bh4[nt >> 1][(nt & 1) * 2]));
                    } else {
                        MMA_F16(acc[mt][nt], ah[mt], (&bh4[nt >> 1][(nt & 1) * 2]));
                    }
                }
            if (PROD == 3) {
                // phase 2: Al*Bh
#pragma unroll
                for (int mt = 0; mt < 4; mt++) {
                    const uint32_t ao =
                        stb + ARR + (uint32_t)((wm * 64 + mt * 16) * 48) + aOff;
                    uint32_t al[4];
                    LDSM_X4(al[0], al[1], al[2], al[3], ao);
#pragma unroll
                    for (int nt = 0; nt < 8; nt++)
                        MMA_BF16(acc[mt][nt], al, (&bh4[nt >> 1][(nt & 1) * 2]));
                }
                // phase 3: Ah*Bl
#pragma unroll
                for (int p = 0; p < 4; p++) {
                    const uint32_t bo = stb + BOFF + ARR +
                        (uint32_t)((wn * 64 + p * 16) * 48) + bOffL;
                    uint32_t bl[4];
                    LDSM_X4(bl[0], bl[1], bl[2], bl[3], bo);
#pragma unroll
                    for (int mt = 0; mt < 4; mt++) {
                        MMA_BF16(acc[mt][2*p],   ah[mt], (&bl[0]));
                        MMA_BF16(acc[mt][2*p+1], ah[mt], (&bl[2]));
                    }
                }
            }
        }

        // ---------------- epilogue ----------------
        float* Cf = (EPI == 0) ? Cfg + (size_t)bz * sC : nullptr;
        bf16*  Ch = (EPI == 2) ? Chg + (size_t)bz * sC : nullptr;
        bf16*  Cl = (EPI == 2) ? Clg + (size_t)bz * sC : nullptr;

#pragma unroll
        for (int mt = 0; mt < 4; mt++) {
            const int r0 = m0 + wm * 64 + mt * 16 + g;
#pragma unroll
            for (int nt = 0; nt < 8; nt++) {
                const int col = n0 + wn * 64 + nt * 8 + tq * 2;
                const float c0 = acc[mt][nt][0], c1 = acc[mt][nt][1];
                const float c2 = acc[mt][nt][2], c3 = acc[mt][nt][3];
                if (EPI == 0) {
                    *(float2*)(Cf + (size_t)r0 * N + col)       = make_float2(c0, c1);
                    *(float2*)(Cf + (size_t)(r0 + 8) * N + col) = make_float2(c2, c3);
                } else {
                    bf16 h0,h1,h2,h3,l0,l1,l2,l3;
                    split2(c0,h0,l0); split2(c1,h1,l1); split2(c2,h2,l2); split2(c3,h3,l3);
                    __nv_bfloat162 tt;
                    tt.x=h0; tt.y=h1; *(__nv_bfloat162*)(Ch + (size_t)r0*N + col)     = tt;
                    tt.x=h2; tt.y=h3; *(__nv_bfloat162*)(Ch + (size_t)(r0+8)*N + col) = tt;
                    tt.x=l0; tt.y=l1; *(__nv_bfloat162*)(Cl + (size_t)r0*N + col)     = tt;
                    tt.x=l2; tt.y=l3; *(__nv_bfloat162*)(Cl + (size_t)(r0+8)*N + col) = tt;
                }
            }
        }
        // all warps must finish smem reads of this tile before any warp
        // issues next tile's cp.async into the same stages
        __syncthreads();
    }
}

// ---------------------------------------------------------------------------
// Variable-length row softmax; loop sized to npad (rows ~1024, not 2048).
// Writes single-fp16 probabilities; zero-fills padding up to pad128(nb).
// ---------------------------------------------------------------------------
__global__ __launch_bounds__(256)
void softmax_rows(const float* __restrict__ scores, const int* __restrict__ nbp,
                  __half* __restrict__ pf)
{
    const int tid = threadIdx.x;
    const int b = blockIdx.x >> 11;
    const int nb = nbp[b];
    const int npad = (nb + 127) & ~127;
    const int ni = (npad + 255) >> 8;       // 256-wide passes actually needed
    const size_t base = (size_t)blockIdx.x * SEQ1;
    const float* row = scores + base;

    float v[8];
    float mx = -3.4e38f;
    for (int i = 0; i < ni; i++) {
        const int j = tid + (i << 8);
        v[i] = (j < nb) ? row[j] : -3.4e38f;
        mx = fmaxf(mx, v[i]);
    }
#pragma unroll
    for (int o = 16; o > 0; o >>= 1)
        mx = fmaxf(mx, __shfl_xor_sync(0xffffffffu, mx, o));

    __shared__ float smax[8];
    __shared__ float ssum[8];
    if ((tid & 31) == 0) smax[tid >> 5] = mx;
    __syncthreads();
    mx = smax[0];
#pragma unroll
    for (int w = 1; w < 8; w++) mx = fmaxf(mx, smax[w]);

    float s = 0.0f;
    for (int i = 0; i < ni; i++) {
        const int j = tid + (i << 8);
        v[i] = (j < nb) ? __expf(v[i] - mx) : 0.0f;
        s += v[i];
    }
#pragma unroll
    for (int o = 16; o > 0; o >>= 1)
        s += __shfl_xor_sync(0xffffffffu, s, o);
    if ((tid & 31) == 0) ssum[tid >> 5] = s;
    __syncthreads();
    s = ssum[0];
#pragma unroll
    for (int w = 1; w < 8; w++) s += ssum[w];

    const float inv = 1.0f / s;
    for (int i = 0; i < ni; i++) {
        const int j = tid + (i << 8);
        if (j < npad)
            pf[base + j] = __float2half((j < nb) ? v[i] * inv : 0.0f);
    }
}

// ---------------------------------------------------------------------------
extern "C" void kernel_launch(void* const* d_in, const int* in_sizes, int n_in,
                              void* d_out, int out_size)
{
    const float*        input1 = (const float*)d_in[0];
    const float*        input2 = (const float*)d_in[1];
    const unsigned int* mask   = (const unsigned int*)d_in[2];
    const float*        weight = (const float*)d_in[3];
    float*              out    = (float*)d_out;

    bf16 *in1h,*in1l,*in2h,*in2l,*wh,*wl,*o1h,*o1l;
    __half *t1f, *pf;
    float *scoresp; int *idxp, *nbp;
    cudaGetSymbolAddress((void**)&idxp, g_idx);
    cudaGetSymbolAddress((void**)&nbp,  g_nb);
    cudaGetSymbolAddress((void**)&in1h, g_in1h);
    cudaGetSymbolAddress((void**)&in1l, g_in1l);
    cudaGetSymbolAddress((void**)&in2h, g_in2h);
    cudaGetSymbolAddress((void**)&in2l, g_in2l);
    cudaGetSymbolAddress((void**)&wh,  g_wh);
    cudaGetSymbolAddress((void**)&wl,  g_wl);
    cudaGetSymbolAddress((void**)&o1h, g_o1h);
    cudaGetSymbolAddress((void**)&o1l, g_o1l);
    cudaGetSymbolAddress((void**)&t1f, g_t1f);
    cudaGetSymbolAddress((void**)&pf,  g_pf);
    cudaGetSymbolAddress((void**)&scoresp, g_scores);

    const int SMEM3 = 98304;   // 4 stages x 4 arrays x 6144B
    const int SMEM1 = 49152;   // 4 stages x 2 arrays x 6144B
    cudaFuncSetAttribute(gemm_mma<2,1,3>, cudaFuncAttributeMaxDynamicSharedMemorySize, SMEM3);
    cudaFuncSetAttribute(gemm_mma<0,2,3>, cudaFuncAttributeMaxDynamicSharedMemorySize, SMEM3);
    cudaFuncSetAttribute(gemm_mma<0,3,1>, cudaFuncAttributeMaxDynamicSharedMemorySize, SMEM1);

    const size_t n1 = (size_t)BATCH * SEQ1 * DIM;

    // 0) mask compaction + operand prep
    build_idx<<<BATCH, 256>>>(mask, idxp, nbp);
    split_kernel<<<(unsigned)(n1 / 1024), 256>>>(input2, in2h, in2l);
    split_kernel<<<(unsigned)((size_t)DIM * DIM / 1024), 256>>>(weight, wh, wl);
    gather_split<<<dim3(SEQ1 / 32, DIM / 32, BATCH), 256>>>(
        input1, idxp, nbp, in1h, in1l, t1f);

    // 1) out1c = in1c @ W^T  (compacted M, split-bf16 out)   tiles 8x16x8
    gemm_mma<2,1,3><<<PGRID, 128, SMEM3>>>(
        in1h, in1l, wh, wl, nullptr, o1h, o1l, nbp,
        DIM, DIM, DIM,
        (size_t)SEQ1 * DIM, 0, (size_t)SEQ1 * DIM,
        DIM / 128, SEQ1 / 128, (DIM / 128) * (SEQ1 / 128) * BATCH);

    // 2) scoresT[b,t,j] = in2[b,t,:] . out1c[b,j,:]  (compacted N) 16x16x8
    gemm_mma<0,2,3><<<PGRID, 128, SMEM3>>>(
        in2h, in2l, o1h, o1l, scoresp, nullptr, nullptr, nbp,
        SEQ1, DIM, DIM,
        (size_t)SEQ2 * DIM, (size_t)SEQ1 * DIM, (size_t)SEQ2 * SEQ1,
        SEQ1 / 128, SEQ2 / 128, (SEQ1 / 128) * (SEQ2 / 128) * BATCH);

    // 3) softmax -> fp16 P
    softmax_rows<<<BATCH * SEQ2, 256>>>(scoresp, nbp, pf);

    // 4) out = P @ in1c  (compacted K, fp16 single product)  tiles 8x16x8
    gemm_mma<0,3,1><<<PGRID, 128, SMEM1>>>(
        (const bf16*)pf, nullptr, (const bf16*)t1f, nullptr,
        out, nullptr, nullptr, nbp,
        DIM, SEQ1, SEQ1,
        (size_t)SEQ2 * SEQ1, (size_t)DIM * SEQ1, (size_t)SEQ2 * DIM,
        DIM / 128, SEQ2 / 128, (DIM / 128) * (SEQ2 / 128) * BATCH);
}

// round 14
// speedup vs baseline: 1.4456x; 1.4456x over previous
#include <cuda_runtime.h>
#include <cuda_bf16.h>
#include <cuda_fp16.h>
#include <stdint.h>

#define BATCH 8
#define SEQ1  2048
#define SEQ2  2048
#define DIM   1024

using bf16 = __nv_bfloat16;

// ---------------- scratch (static __device__, zero-init, no allocation) -----
__device__ int    g_idx[BATCH * SEQ1];              // compacted s indices
__device__ int    g_nb[BATCH];                      // # unmasked rows per batch
__device__ bf16   g_in1h[(size_t)BATCH*SEQ1*DIM];   // compacted input1 split
__device__ bf16   g_in1l[(size_t)BATCH*SEQ1*DIM];
__device__ bf16   g_in2h[(size_t)BATCH*SEQ2*DIM];
__device__ bf16   g_in2l[(size_t)BATCH*SEQ2*DIM];
__device__ bf16   g_wh[(size_t)DIM*DIM];
__device__ bf16   g_wl[(size_t)DIM*DIM];
__device__ bf16   g_o1h[(size_t)BATCH*SEQ1*DIM];    // compacted out1 split
__device__ bf16   g_o1l[(size_t)BATCH*SEQ1*DIM];
__device__ __half g_t1f[(size_t)BATCH*DIM*SEQ1];    // compacted input1^T fp16
__device__ float  g_scores[(size_t)BATCH*SEQ2*SEQ1];
__device__ __half g_pf[(size_t)BATCH*SEQ2*SEQ1];    // probabilities fp16

__device__ __forceinline__ void split2(float x, bf16 &h, bf16 &l) {
    h = __float2bfloat16(x);
    l = __float2bfloat16(x - __bfloat162float(h));
}

// ---------------- mask compaction: per-batch ascending index list -----------
__global__ __launch_bounds__(256)
void build_idx(const unsigned* __restrict__ mask, int* __restrict__ idx,
               int* __restrict__ nb)
{
    const int b = blockIdx.x, tid = threadIdx.x;
    const int lane = tid & 31, wid = tid >> 5;
    const unsigned* mk = mask + (size_t)b * SEQ1;
    __shared__ int wsum[8];

    int bits[8], c = 0;
#pragma unroll
    for (int k = 0; k < 8; k++) {
        bits[k] = (mk[tid * 8 + k] != 0u) ? 1 : 0;
        c += bits[k];
    }
    int pre = c;
#pragma unroll
    for (int o = 1; o < 32; o <<= 1) {
        int n = __shfl_up_sync(0xffffffffu, pre, o);
        if (lane >= o) pre += n;
    }
    if (lane == 31) wsum[wid] = pre;
    __syncthreads();
    int woff = 0;
    for (int w = 0; w < wid; w++) woff += wsum[w];
    int pos = woff + pre - c;
#pragma unroll
    for (int k = 0; k < 8; k++)
        if (bits[k]) idx[b * SEQ1 + pos++] = tid * 8 + k;
    if (tid == 255) nb[b] = woff + pre;
}

// ---------------- split (fp32 -> hi/lo bf16), plain -------------------------
__global__ __launch_bounds__(256) void split_kernel(const float* __restrict__ x,
                                                    bf16* __restrict__ h,
                                                    bf16* __restrict__ l) {
    size_t i = ((size_t)blockIdx.x * 256 + threadIdx.x) * 4;
    float4 v = *(const float4*)(x + i);
    bf16 h0,h1,h2,h3,l0,l1,l2,l3;
    split2(v.x,h0,l0); split2(v.y,h1,l1); split2(v.z,h2,l2); split2(v.w,h3,l3);
    __nv_bfloat162 a, b;
    a.x=h0; a.y=h1; b.x=h2; b.y=h3;
    ((__nv_bfloat162*)(h+i))[0] = a; ((__nv_bfloat162*)(h+i))[1] = b;
    a.x=l0; a.y=l1; b.x=l2; b.y=l3;
    ((__nv_bfloat162*)(l+i))[0] = a; ((__nv_bfloat162*)(l+i))[1] = b;
}

// ---------------- gather + split + transpose of input1 (compacted) ----------
__global__ __launch_bounds__(256)
void gather_split(const float* __restrict__ x, const int* __restrict__ idxp,
                  const int* __restrict__ nbp,
                  bf16* __restrict__ ch, bf16* __restrict__ cl,
                  __half* __restrict__ tf)
{
    const int b  = blockIdx.z;
    const int j0 = blockIdx.x * 32, d0 = blockIdx.y * 32;
    const int nb = nbp[b];
    const int npad = (nb + 127) & ~127;
    if (j0 >= npad) return;

    const int tx = threadIdx.x & 31, ty = threadIdx.x >> 5;
    __shared__ float t[32][33];
    __shared__ int rows[32];
    if (threadIdx.x < 32)
        rows[threadIdx.x] =
            (j0 + threadIdx.x < nb) ? idxp[b * SEQ1 + j0 + threadIdx.x] : -1;
    __syncthreads();
#pragma unroll
    for (int k = 0; k < 4; k++) {
        const int j = ty + 8 * k;
        const int s = rows[j];
        t[j][tx] = (s >= 0) ? x[((size_t)b * SEQ1 + s) * DIM + d0 + tx] : 0.0f;
    }
    __syncthreads();
#pragma unroll
    for (int k = 0; k < 4; k++) {
        const int j = ty + 8 * k;
        bf16 h, l; split2(t[j][tx], h, l);
        const size_t o = ((size_t)b * SEQ1 + j0 + j) * DIM + d0 + tx;
        ch[o] = h; cl[o] = l;
    }
#pragma unroll
    for (int k = 0; k < 4; k++) {
        const size_t o = ((size_t)b * DIM + d0 + ty + 8 * k) * SEQ1 + j0 + tx;
        tf[o] = __float2half(t[tx][ty + 8 * k]);
    }
}

// ---------------- PTX helpers ----------------
#define CP16(dst, src) asm volatile("cp.async.cg.shared.global [%0], [%1], 16;\n" :: "r"(dst), "l"(src))
#define CP_COMMIT()    asm volatile("cp.async.commit_group;\n")
#define CP_WAIT2()     asm volatile("cp.async.wait_group 2;\n")
#define CP_WAIT1()     asm volatile("cp.async.wait_group 1;\n")
#define CP_WAIT0()     asm volatile("cp.async.wait_group 0;\n")

#define MMA_BF16(d, a, b) asm volatile( \
  "mma.sync.aligned.m16n8k16.row.col.f32.bf16.bf16.f32 " \
  "{%0,%1,%2,%3},{%4,%5,%6,%7},{%8,%9},{%0,%1,%2,%3};\n" \
  : "+f"(d[0]), "+f"(d[1]), "+f"(d[2]), "+f"(d[3]) \
  : "r"(a[0]), "r"(a[1]), "r"(a[2]), "r"(a[3]), "r"(b[0]), "r"(b[1]))

#define MMA_F16(d, a, b) asm volatile( \
  "mma.sync.aligned.m16n8k16.row.col.f32.f16.f16.f32 " \
  "{%0,%1,%2,%3},{%4,%5,%6,%7},{%8,%9},{%0,%1,%2,%3};\n" \
  : "+f"(d[0]), "+f"(d[1]), "+f"(d[2]), "+f"(d[3]) \
  : "r"(a[0]), "r"(a[1]), "r"(a[2]), "r"(a[3]), "r"(b[0]), "r"(b[1]))

#define LDSM_X4(r0, r1, r2, r3, addr) asm volatile( \
  "ldmatrix.sync.aligned.m8n8.x4.shared.b16 {%0,%1,%2,%3}, [%4];\n" \
  : "=r"(r0), "=r"(r1), "=r"(r2), "=r"(r3) : "r"(addr))

// ---------------------------------------------------------------------------
// HMMA NT GEMM (round-10 proven core, best measured config): C = A*B^T.
// 128x128 tile, BK=16, 256 threads = 8 warps (64x32 each), 4-stage cp.async,
// ldmatrix.x4 fragments, product-major MMA ordering.
//   PROD=3: split-bf16 3-product, 4 operand arrays.  PROD=1: fp16 1-product.
//   EPI=0: fp32 out.  EPI=2: split-bf16 out.
//   BND=1: skip m0 >= pad128(nb).  BND=2: skip n0 >= pad128(nb).
//   BND=3: K = pad16(nb).   Ks = row stride of A/B.
// ---------------------------------------------------------------------------
template<int EPI, int BND, int PROD>
__global__ __launch_bounds__(256, 2)
void gemm_mma(const bf16* __restrict__ Ahg, const bf16* __restrict__ Alg,
              const bf16* __restrict__ Bhg, const bf16* __restrict__ Blg,
              float* __restrict__ Cfg, bf16* __restrict__ Chg, bf16* __restrict__ Clg,
              const int* __restrict__ nbp,
              int N, int K, int Ks,
              size_t sA, size_t sB, size_t sC)
{
    extern __shared__ __align__(16) char dsm[];
    const uint32_t smem0 = (uint32_t)__cvta_generic_to_shared(dsm);
    constexpr uint32_t ARR = 6144u;                       // 128 x 24 halves x 2B
    constexpr uint32_t NARR = (PROD == 3) ? 4u : 2u;
    constexpr uint32_t STAGE = NARR * ARR;
    constexpr uint32_t BOFF = (PROD == 3) ? 2u * ARR : ARR;

    const int tid  = threadIdx.x;
    const int warp = tid >> 5, lane = tid & 31;
    const int wm = warp >> 2, wn = warp & 3;
    const int g  = lane >> 2, tq = lane & 3;
    const int bz = blockIdx.z;
    const int m0 = blockIdx.y * 128, n0 = blockIdx.x * 128;

    int Klogic = K;
    if (BND) {
        const int nb = nbp[bz];
        const int npad = (nb + 127) & ~127;
        if (BND == 1 && m0 >= npad) return;
        if (BND == 2 && n0 >= npad) return;
        if (BND == 3) Klogic = (nb + 15) & ~15;
    }

    const bf16* Ah = Ahg + (size_t)bz * sA + (size_t)m0 * Ks;
    const bf16* Al = (PROD == 3) ? Alg + (size_t)bz * sA + (size_t)m0 * Ks : nullptr;
    const bf16* Bh = Bhg + (size_t)bz * sB + (size_t)n0 * Ks;
    const bf16* Bl = (PROD == 3) ? Blg + (size_t)bz * sB + (size_t)n0 * Ks : nullptr;

    const int r_ = tid >> 1, u_ = tid & 1;
    const uint32_t offc = (uint32_t)(r_ * 48 + u_ * 16);

    const uint32_t aOff =
        (uint32_t)(((lane & 15) * 24 + ((lane >> 4) & 1) * 8) * 2);
    const uint32_t bOffL =
        (uint32_t)((((lane & 7) + ((lane >> 4) & 1) * 8) * 24 +
                    ((lane >> 3) & 1) * 8) * 2);

    float acc[4][4][4];
#pragma unroll
    for (int mt = 0; mt < 4; mt++)
#pragma unroll
        for (int nt = 0; nt < 4; nt++)
#pragma unroll
            for (int c = 0; c < 4; c++) acc[mt][nt][c] = 0.0f;

    const int NC = Klogic >> 4;

    auto issue = [&](int stg, int kk) {
        const uint32_t sb_ = smem0 + (uint32_t)stg * STAGE;
        const size_t go_ = (size_t)r_ * Ks + kk + u_ * 8;
        CP16(sb_ + offc, Ah + go_);
        if (PROD == 3) CP16(sb_ + ARR + offc, Al + go_);
        CP16(sb_ + BOFF + offc, Bh + go_);
        if (PROD == 3) CP16(sb_ + 3u * ARR + offc, Bl + go_);
        CP_COMMIT();
    };

    // 4-stage prologue: 3 chunks in flight
    issue(0, 0);
    if (NC > 1) issue(1, 16);
    if (NC > 2) issue(2, 32);

    for (int i = 0; i < NC; i++) {
        if (i + 2 < NC)      { CP_WAIT2(); }
        else if (i + 1 < NC) { CP_WAIT1(); }
        else                 { CP_WAIT0(); }
        __syncthreads();
        if (i + 3 < NC) issue((i + 3) & 3, (i + 3) << 4);

        const uint32_t stb = smem0 + (uint32_t)(i & 3) * STAGE;

        uint32_t bh4[2][4], bl4[2][4];
#pragma unroll
        for (int p = 0; p < 2; p++) {
            const uint32_t bo =
                stb + BOFF + (uint32_t)((wn * 32 + p * 16) * 48) + bOffL;
            LDSM_X4(bh4[p][0], bh4[p][1], bh4[p][2], bh4[p][3], bo);
            if (PROD == 3)
                LDSM_X4(bl4[p][0], bl4[p][1], bl4[p][2], bl4[p][3], bo + ARR);
        }
        uint32_t ah[4][4];
#pragma unroll
        for (int mt = 0; mt < 4; mt++) {
            const uint32_t ao =
                stb + (uint32_t)((wm * 64 + mt * 16) * 48) + aOff;
            LDSM_X4(ah[mt][0], ah[mt][1], ah[mt][2], ah[mt][3], ao);
        }

        // phase 1: Ah*Bh
#pragma unroll
        for (int mt = 0; mt < 4; mt++)
#pragma unroll
            for (int nt = 0; nt < 4; nt++) {
                if (PROD == 3) {
                    MMA_BF16(acc[mt][nt], ah[mt], (&bh4[nt >> 1][(nt & 1) * 2]));
                } else {
                    MMA_F16(acc[mt][nt], ah[mt], (&bh4[nt >> 1][(nt & 1) * 2]));
                }
            }
        if (PROD == 3) {
            // phase 2: Ah*Bl
#pragma unroll
            for (int mt = 0; mt < 4; mt++)
#pragma unroll
                for (int nt = 0; nt < 4; nt++)
                    MMA_BF16(acc[mt][nt], ah[mt], (&bl4[nt >> 1][(nt & 1) * 2]));
            // phase 3: Al*Bh
#pragma unroll
            for (int mt = 0; mt < 4; mt++) {
                const uint32_t ao =
                    stb + ARR + (uint32_t)((wm * 64 + mt * 16) * 48) + aOff;
                uint32_t al[4];
                LDSM_X4(al[0], al[1], al[2], al[3], ao);
#pragma unroll
                for (int nt = 0; nt < 4; nt++)
                    MMA_BF16(acc[mt][nt], al, (&bh4[nt >> 1][(nt & 1) * 2]));
            }
        }
    }

    // ---------------- epilogue ----------------
    float* Cf = (EPI == 0) ? Cfg + (size_t)bz * sC : nullptr;
    bf16*  Ch = (EPI == 2) ? Chg + (size_t)bz * sC : nullptr;
    bf16*  Cl = (EPI == 2) ? Clg + (size_t)bz * sC : nullptr;

#pragma unroll
    for (int mt = 0; mt < 4; mt++) {
        const int r0 = m0 + wm * 64 + mt * 16 + g;
#pragma unroll
        for (int nt = 0; nt < 4; nt++) {
            const int col = n0 + wn * 32 + nt * 8 + tq * 2;
            const float c0 = acc[mt][nt][0], c1 = acc[mt][nt][1];
            const float c2 = acc[mt][nt][2], c3 = acc[mt][nt][3];
            if (EPI == 0) {
                *(float2*)(Cf + (size_t)r0 * N + col)       = make_float2(c0, c1);
                *(float2*)(Cf + (size_t)(r0 + 8) * N + col) = make_float2(c2, c3);
            } else {
                bf16 h0,h1,h2,h3,l0,l1,l2,l3;
                split2(c0,h0,l0); split2(c1,h1,l1); split2(c2,h2,l2); split2(c3,h3,l3);
                __nv_bfloat162 t;
                t.x=h0; t.y=h1; *(__nv_bfloat162*)(Ch + (size_t)r0*N + col)     = t;
                t.x=h2; t.y=h3; *(__nv_bfloat162*)(Ch + (size_t)(r0+8)*N + col) = t;
                t.x=l0; t.y=l1; *(__nv_bfloat162*)(Cl + (size_t)r0*N + col)     = t;
                t.x=l2; t.y=l3; *(__nv_bfloat162*)(Cl + (size_t)(r0+8)*N + col) = t;
            }
        }
    }
}

// ---------------------------------------------------------------------------
// Variable-length row softmax over compacted scores [b,t,j], j in [0, nb).
// Fully-unrolled loop, but passes with j >= npad are skipped entirely
// (rows are ~1024-1152 after compaction, so ~half the passes do no work).
// Writes single-fp16 probabilities; zero-fills padding up to pad128(nb).
// ---------------------------------------------------------------------------
__global__ __launch_bounds__(256)
void softmax_rows(const float* __restrict__ scores, const int* __restrict__ nbp,
                  __half* __restrict__ pf)
{
    const int tid = threadIdx.x;
    const int b = blockIdx.x >> 11;         // SEQ2 = 2048 rows per batch
    const int nb = nbp[b];
    const int npad = (nb + 127) & ~127;
    const size_t base = (size_t)blockIdx.x * SEQ1;
    const float* row = scores + base;

    float v[8];
    float mx = -3.4e38f;
#pragma unroll
    for (int i = 0; i < 8; i++) {
        const int j = tid + (i << 8);
        v[i] = (j < nb) ? row[j] : -3.4e38f;   // predicated; no read past nb
        if (j >= npad) continue;               // skip dead passes
        mx = fmaxf(mx, v[i]);
    }
#pragma unroll
    for (int o = 16; o > 0; o >>= 1)
        mx = fmaxf(mx, __shfl_xor_sync(0xffffffffu, mx, o));

    __shared__ float smax[8];
    __shared__ float ssum[8];
    if ((tid & 31) == 0) smax[tid >> 5] = mx;
    __syncthreads();
    mx = smax[0];
#pragma unroll
    for (int w = 1; w < 8; w++) mx = fmaxf(mx, smax[w]);

    float s = 0.0f;
#pragma unroll
    for (int i = 0; i < 8; i++) {
        const int j = tid + (i << 8);
        v[i] = (j < nb) ? __expf(v[i] - mx) : 0.0f;
        s += v[i];
    }
#pragma unroll
    for (int o = 16; o > 0; o >>= 1)
        s += __shfl_xor_sync(0xffffffffu, s, o);
    if ((tid & 31) == 0) ssum[tid >> 5] = s;
    __syncthreads();
    s = ssum[0];
#pragma unroll
    for (int w = 1; w < 8; w++) s += ssum[w];

    const float inv = 1.0f / s;
#pragma unroll
    for (int i = 0; i < 8; i++) {
        const int j = tid + (i << 8);
        if (j < npad)
            pf[base + j] = __float2half((j < nb) ? v[i] * inv : 0.0f);
    }
}

// ---------------------------------------------------------------------------
extern "C" void kernel_launch(void* const* d_in, const int* in_sizes, int n_in,
                              void* d_out, int out_size)
{
    const float*        input1 = (const float*)d_in[0];          // [B,S1,D]
    const float*        input2 = (const float*)d_in[1];          // [B,S2,D]
    const unsigned int* mask   = (const unsigned int*)d_in[2];   // [B,S1] words
    const float*        weight = (const float*)d_in[3];          // [D,D]
    float*              out    = (float*)d_out;                  // [B,S2,D]

    bf16 *in1h,*in1l,*in2h,*in2l,*wh,*wl,*o1h,*o1l;
    __half *t1f, *pf;
    float *scoresp; int *idxp, *nbp;
    cudaGetSymbolAddress((void**)&idxp, g_idx);
    cudaGetSymbolAddress((void**)&nbp,  g_nb);
    cudaGetSymbolAddress((void**)&in1h, g_in1h);
    cudaGetSymbolAddress((void**)&in1l, g_in1l);
    cudaGetSymbolAddress((void**)&in2h, g_in2h);
    cudaGetSymbolAddress((void**)&in2l, g_in2l);
    cudaGetSymbolAddress((void**)&wh,  g_wh);
    cudaGetSymbolAddress((void**)&wl,  g_wl);
    cudaGetSymbolAddress((void**)&o1h, g_o1h);
    cudaGetSymbolAddress((void**)&o1l, g_o1l);
    cudaGetSymbolAddress((void**)&t1f, g_t1f);
    cudaGetSymbolAddress((void**)&pf,  g_pf);
    cudaGetSymbolAddress((void**)&scoresp, g_scores);

    const int SMEM3 = 98304;   // PROD=3: 4 stages x 4 arrays x 6144B
    const int SMEM1 = 49152;   // PROD=1: 4 stages x 2 arrays x 6144B
    cudaFuncSetAttribute(gemm_mma<2,1,3>, cudaFuncAttributeMaxDynamicSharedMemorySize, SMEM3);
    cudaFuncSetAttribute(gemm_mma<0,2,3>, cudaFuncAttributeMaxDynamicSharedMemorySize, SMEM3);
    cudaFuncSetAttribute(gemm_mma<0,3,1>, cudaFuncAttributeMaxDynamicSharedMemorySize, SMEM1);

    const size_t n1 = (size_t)BATCH * SEQ1 * DIM;

    // 0) mask compaction + operand prep
    build_idx<<<BATCH, 256>>>(mask, idxp, nbp);
    split_kernel<<<(unsigned)(n1 / 1024), 256>>>(input2, in2h, in2l);
    split_kernel<<<(unsigned)((size_t)DIM * DIM / 1024), 256>>>(weight, wh, wl);
    gather_split<<<dim3(SEQ1 / 32, DIM / 32, BATCH), 256>>>(
        input1, idxp, nbp, in1h, in1l, t1f);

    // 1) out1c[b,j,:] = in1c[b,j,:] @ W^T  (compacted M, split-bf16 out)
    gemm_mma<2,1,3><<<dim3(DIM / 128, SEQ1 / 128, BATCH), 256, SMEM3>>>(
        in1h, in1l, wh, wl, nullptr, o1h, o1l, nbp,
        DIM, DIM, DIM,
        (size_t)SEQ1 * DIM, 0, (size_t)SEQ1 * DIM);

    // 2) scoresT[b,t,j] = in2[b,t,:] . out1c[b,j,:]  (compacted N)
    gemm_mma<0,2,3><<<dim3(SEQ1 / 128, SEQ2 / 128, BATCH), 256, SMEM3>>>(
        in2h, in2l, o1h, o1l, scoresp, nullptr, nullptr, nbp,
        SEQ1, DIM, DIM,
        (size_t)SEQ2 * DIM, (size_t)SEQ1 * DIM, (size_t)SEQ2 * SEQ1);

    // 3) softmax over compacted j -> single fp16 P (zero-padded)
    softmax_rows<<<BATCH * SEQ2, 256>>>(scoresp, nbp, pf);

    // 4) out[b,t,d] = sum_j P[b,t,j] * in1c[b,j,d]  (compacted K, fp16 1-prod)
    gemm_mma<0,3,1><<<dim3(DIM / 128, SEQ2 / 128, BATCH), 256, SMEM1>>>(
        (const bf16*)pf, nullptr, (const bf16*)t1f, nullptr,
        out, nullptr, nullptr, nbp,
        DIM, SEQ1, SEQ1,
        (size_t)SEQ2 * SEQ1, (size_t)DIM * SEQ1, (size_t)SEQ2 * DIM);
}

// round 15
// speedup vs baseline: 1.4625x; 1.0117x over previous
#include <cuda_runtime.h>
#include <cuda_bf16.h>
#include <cuda_fp16.h>
#include <stdint.h>

#define BATCH 8
#define SEQ1  2048
#define SEQ2  2048
#define DIM   1024

using bf16 = __nv_bfloat16;

// ---------------- scratch (static __device__, zero-init, no allocation) -----
__device__ int    g_idx[BATCH * SEQ1];              // compacted s indices
__device__ int    g_nb[BATCH];                      // # unmasked rows per batch
__device__ bf16   g_in1h[(size_t)BATCH*SEQ1*DIM];   // compacted input1 split
__device__ bf16   g_in1l[(size_t)BATCH*SEQ1*DIM];
__device__ bf16   g_in2h[(size_t)BATCH*SEQ2*DIM];
__device__ bf16   g_in2l[(size_t)BATCH*SEQ2*DIM];
__device__ bf16   g_wh[(size_t)DIM*DIM];
__device__ bf16   g_wl[(size_t)DIM*DIM];
__device__ bf16   g_o1h[(size_t)BATCH*SEQ1*DIM];    // compacted out1 split
__device__ bf16   g_o1l[(size_t)BATCH*SEQ1*DIM];
__device__ __half g_t1f[(size_t)BATCH*DIM*SEQ1];    // compacted input1^T fp16
__device__ float  g_scores[(size_t)BATCH*SEQ2*SEQ1];
__device__ __half g_pf[(size_t)BATCH*SEQ2*SEQ1];    // probabilities fp16

__device__ __forceinline__ void split2(float x, bf16 &h, bf16 &l) {
    h = __float2bfloat16(x);
    l = __float2bfloat16(x - __bfloat162float(h));
}

// ---------------- mask compaction: per-batch ascending index list -----------
__global__ __launch_bounds__(256)
void build_idx(const unsigned* __restrict__ mask, int* __restrict__ idx,
               int* __restrict__ nb)
{
    const int b = blockIdx.x, tid = threadIdx.x;
    const int lane = tid & 31, wid = tid >> 5;
    const unsigned* mk = mask + (size_t)b * SEQ1;
    __shared__ int wsum[8];

    int bits[8], c = 0;
#pragma unroll
    for (int k = 0; k < 8; k++) {
        bits[k] = (mk[tid * 8 + k] != 0u) ? 1 : 0;
        c += bits[k];
    }
    int pre = c;
#pragma unroll
    for (int o = 1; o < 32; o <<= 1) {
        int n = __shfl_up_sync(0xffffffffu, pre, o);
        if (lane >= o) pre += n;
    }
    if (lane == 31) wsum[wid] = pre;
    __syncthreads();
    int woff = 0;
    for (int w = 0; w < wid; w++) woff += wsum[w];
    int pos = woff + pre - c;
#pragma unroll
    for (int k = 0; k < 8; k++)
        if (bits[k]) idx[b * SEQ1 + pos++] = tid * 8 + k;
    if (tid == 255) nb[b] = woff + pre;
}

// ---------------- split (fp32 -> hi/lo bf16), plain -------------------------
__global__ __launch_bounds__(256) void split_kernel(const float* __restrict__ x,
                                                    bf16* __restrict__ h,
                                                    bf16* __restrict__ l) {
    size_t i = ((size_t)blockIdx.x * 256 + threadIdx.x) * 4;
    float4 v = *(const float4*)(x + i);
    bf16 h0,h1,h2,h3,l0,l1,l2,l3;
    split2(v.x,h0,l0); split2(v.y,h1,l1); split2(v.z,h2,l2); split2(v.w,h3,l3);
    __nv_bfloat162 a, b;
    a.x=h0; a.y=h1; b.x=h2; b.y=h3;
    ((__nv_bfloat162*)(h+i))[0] = a; ((__nv_bfloat162*)(h+i))[1] = b;
    a.x=l0; a.y=l1; b.x=l2; b.y=l3;
    ((__nv_bfloat162*)(l+i))[0] = a; ((__nv_bfloat162*)(l+i))[1] = b;
}

// ---------------- gather + split + transpose of input1 (compacted) ----------
// Vectorized: 32x64 tile, float2 loads, bf16x2 stores (split), half2 stores
// (transpose, paired over j -> coalesced 4B writes).
__global__ __launch_bounds__(256)
void gather_split(const float* __restrict__ x, const int* __restrict__ idxp,
                  const int* __restrict__ nbp,
                  bf16* __restrict__ ch, bf16* __restrict__ cl,
                  __half* __restrict__ tf)
{
    const int b  = blockIdx.z;
    const int j0 = blockIdx.x * 32, d0 = blockIdx.y * 64;
    const int nb = nbp[b];
    const int npad = (nb + 127) & ~127;
    if (j0 >= npad) return;

    __shared__ float t[32][65];
    __shared__ int rows[32];
    const int tid = threadIdx.x;
    if (tid < 32)
        rows[tid] = (j0 + tid < nb) ? idxp[b * SEQ1 + j0 + tid] : -1;
    __syncthreads();

    // load 32 rows x 64 cols (float2 per thread per pass)
    {
        const int c2 = tid & 31;          // col pair -> cols 2c2, 2c2+1
        const int rq = tid >> 5;          // 0..7
#pragma unroll
        for (int k = 0; k < 4; k++) {
            const int j = rq + 8 * k;
            const int s = rows[j];
            float2 v = make_float2(0.0f, 0.0f);
            if (s >= 0)
                v = *(const float2*)(x + ((size_t)b * SEQ1 + s) * DIM + d0 + 2 * c2);
            t[j][2 * c2]     = v.x;
            t[j][2 * c2 + 1] = v.y;
        }
    }
    __syncthreads();

    // normal orientation: bf16 split, paired stores
    {
        const int c2 = tid & 31;
        const int rq = tid >> 5;
#pragma unroll
        for (int k = 0; k < 4; k++) {
            const int j = rq + 8 * k;
            bf16 h0,l0,h1,l1;
            split2(t[j][2*c2],     h0, l0);
            split2(t[j][2*c2 + 1], h1, l1);
            const size_t o = ((size_t)b * SEQ1 + j0 + j) * DIM + d0 + 2 * c2;
            __nv_bfloat162 hh; hh.x = h0; hh.y = h1;
            __nv_bfloat162 ll; ll.x = l0; ll.y = l1;
            *(__nv_bfloat162*)(ch + o) = hh;
            *(__nv_bfloat162*)(cl + o) = ll;
        }
    }

    // transposed orientation: fp16, half2 stores over j pairs (coalesced)
    {
        const int jp = tid & 15;          // j pair -> j = 2jp, 2jp+1
        const int dd = tid >> 4;          // 0..15
#pragma unroll
        for (int k = 0; k < 4; k++) {
            const int d = dd + 16 * k;
            __half2 v;
            v.x = __float2half(t[2 * jp][d]);
            v.y = __float2half(t[2 * jp + 1][d]);
            const size_t o = ((size_t)b * DIM + d0 + d) * SEQ1 + j0 + 2 * jp;
            *(__half2*)(tf + o) = v;
        }
    }
}

// ---------------- PTX helpers ----------------
#define CP16(dst, src) asm volatile("cp.async.cg.shared.global [%0], [%1], 16;\n" :: "r"(dst), "l"(src))
#define CP_COMMIT()    asm volatile("cp.async.commit_group;\n")
#define CP_WAIT2()     asm volatile("cp.async.wait_group 2;\n")
#define CP_WAIT1()     asm volatile("cp.async.wait_group 1;\n")
#define CP_WAIT0()     asm volatile("cp.async.wait_group 0;\n")

#define MMA_BF16(d, a, b) asm volatile( \
  "mma.sync.aligned.m16n8k16.row.col.f32.bf16.bf16.f32 " \
  "{%0,%1,%2,%3},{%4,%5,%6,%7},{%8,%9},{%0,%1,%2,%3};\n" \
  : "+f"(d[0]), "+f"(d[1]), "+f"(d[2]), "+f"(d[3]) \
  : "r"(a[0]), "r"(a[1]), "r"(a[2]), "r"(a[3]), "r"(b[0]), "r"(b[1]))

#define MMA_F16(d, a, b) asm volatile( \
  "mma.sync.aligned.m16n8k16.row.col.f32.f16.f16.f32 " \
  "{%0,%1,%2,%3},{%4,%5,%6,%7},{%8,%9},{%0,%1,%2,%3};\n" \
  : "+f"(d[0]), "+f"(d[1]), "+f"(d[2]), "+f"(d[3]) \
  : "r"(a[0]), "r"(a[1]), "r"(a[2]), "r"(a[3]), "r"(b[0]), "r"(b[1]))

#define LDSM_X4(r0, r1, r2, r3, addr) asm volatile( \
  "ldmatrix.sync.aligned.m8n8.x4.shared.b16 {%0,%1,%2,%3}, [%4];\n" \
  : "=r"(r0), "=r"(r1), "=r"(r2), "=r"(r3) : "r"(addr))

// ---------------------------------------------------------------------------
// HMMA NT GEMM (proven 752us core, unchanged): C = A*B^T.
// 128x128 tile, BK=16, 256 threads = 8 warps (64x32 each), 4-stage cp.async,
// ldmatrix.x4 fragments, product-major MMA ordering.
//   PROD=3: split-bf16 3-product, 4 operand arrays.  PROD=1: fp16 1-product.
//   EPI=0: fp32 out.  EPI=2: split-bf16 out.
//   BND=1: skip m0 >= pad128(nb).  BND=2: skip n0 >= pad128(nb).
//   BND=3: K = pad16(nb).   Ks = row stride of A/B.
// ---------------------------------------------------------------------------
template<int EPI, int BND, int PROD>
__global__ __launch_bounds__(256, 2)
void gemm_mma(const bf16* __restrict__ Ahg, const bf16* __restrict__ Alg,
              const bf16* __restrict__ Bhg, const bf16* __restrict__ Blg,
              float* __restrict__ Cfg, bf16* __restrict__ Chg, bf16* __restrict__ Clg,
              const int* __restrict__ nbp,
              int N, int K, int Ks,
              size_t sA, size_t sB, size_t sC)
{
    extern __shared__ __align__(16) char dsm[];
    const uint32_t smem0 = (uint32_t)__cvta_generic_to_shared(dsm);
    constexpr uint32_t ARR = 6144u;                       // 128 x 24 halves x 2B
    constexpr uint32_t NARR = (PROD == 3) ? 4u : 2u;
    constexpr uint32_t STAGE = NARR * ARR;
    constexpr uint32_t BOFF = (PROD == 3) ? 2u * ARR : ARR;

    const int tid  = threadIdx.x;
    const int warp = tid >> 5, lane = tid & 31;
    const int wm = warp >> 2, wn = warp & 3;
    const int g  = lane >> 2, tq = lane & 3;
    const int bz = blockIdx.z;
    const int m0 = blockIdx.y * 128, n0 = blockIdx.x * 128;

    int Klogic = K;
    if (BND) {
        const int nb = nbp[bz];
        const int npad = (nb + 127) & ~127;
        if (BND == 1 && m0 >= npad) return;
        if (BND == 2 && n0 >= npad) return;
        if (BND == 3) Klogic = (nb + 15) & ~15;
    }

    const bf16* Ah = Ahg + (size_t)bz * sA + (size_t)m0 * Ks;
    const bf16* Al = (PROD == 3) ? Alg + (size_t)bz * sA + (size_t)m0 * Ks : nullptr;
    const bf16* Bh = Bhg + (size_t)bz * sB + (size_t)n0 * Ks;
    const bf16* Bl = (PROD == 3) ? Blg + (size_t)bz * sB + (size_t)n0 * Ks : nullptr;

    const int r_ = tid >> 1, u_ = tid & 1;
    const uint32_t offc = (uint32_t)(r_ * 48 + u_ * 16);

    const uint32_t aOff =
        (uint32_t)(((lane & 15) * 24 + ((lane >> 4) & 1) * 8) * 2);
    const uint32_t bOffL =
        (uint32_t)((((lane & 7) + ((lane >> 4) & 1) * 8) * 24 +
                    ((lane >> 3) & 1) * 8) * 2);

    float acc[4][4][4];
#pragma unroll
    for (int mt = 0; mt < 4; mt++)
#pragma unroll
        for (int nt = 0; nt < 4; nt++)
#pragma unroll
            for (int c = 0; c < 4; c++) acc[mt][nt][c] = 0.0f;

    const int NC = Klogic >> 4;

    auto issue = [&](int stg, int kk) {
        const uint32_t sb_ = smem0 + (uint32_t)stg * STAGE;
        const size_t go_ = (size_t)r_ * Ks + kk + u_ * 8;
        CP16(sb_ + offc, Ah + go_);
        if (PROD == 3) CP16(sb_ + ARR + offc, Al + go_);
        CP16(sb_ + BOFF + offc, Bh + go_);
        if (PROD == 3) CP16(sb_ + 3u * ARR + offc, Bl + go_);
        CP_COMMIT();
    };

    // 4-stage prologue: 3 chunks in flight
    issue(0, 0);
    if (NC > 1) issue(1, 16);
    if (NC > 2) issue(2, 32);

    for (int i = 0; i < NC; i++) {
        if (i + 2 < NC)      { CP_WAIT2(); }
        else if (i + 1 < NC) { CP_WAIT1(); }
        else                 { CP_WAIT0(); }
        __syncthreads();
        if (i + 3 < NC) issue((i + 3) & 3, (i + 3) << 4);

        const uint32_t stb = smem0 + (uint32_t)(i & 3) * STAGE;

        uint32_t bh4[2][4], bl4[2][4];
#pragma unroll
        for (int p = 0; p < 2; p++) {
            const uint32_t bo =
                stb + BOFF + (uint32_t)((wn * 32 + p * 16) * 48) + bOffL;
            LDSM_X4(bh4[p][0], bh4[p][1], bh4[p][2], bh4[p][3], bo);
            if (PROD == 3)
                LDSM_X4(bl4[p][0], bl4[p][1], bl4[p][2], bl4[p][3], bo + ARR);
        }
        uint32_t ah[4][4];
#pragma unroll
        for (int mt = 0; mt < 4; mt++) {
            const uint32_t ao =
                stb + (uint32_t)((wm * 64 + mt * 16) * 48) + aOff;
            LDSM_X4(ah[mt][0], ah[mt][1], ah[mt][2], ah[mt][3], ao);
        }

        // phase 1: Ah*Bh
#pragma unroll
        for (int mt = 0; mt < 4; mt++)
#pragma unroll
            for (int nt = 0; nt < 4; nt++) {
                if (PROD == 3) {
                    MMA_BF16(acc[mt][nt], ah[mt], (&bh4[nt >> 1][(nt & 1) * 2]));
                } else {
                    MMA_F16(acc[mt][nt], ah[mt], (&bh4[nt >> 1][(nt & 1) * 2]));
                }
            }
        if (PROD == 3) {
            // phase 2: Ah*Bl
#pragma unroll
            for (int mt = 0; mt < 4; mt++)
#pragma unroll
                for (int nt = 0; nt < 4; nt++)
                    MMA_BF16(acc[mt][nt], ah[mt], (&bl4[nt >> 1][(nt & 1) * 2]));
            // phase 3: Al*Bh
#pragma unroll
            for (int mt = 0; mt < 4; mt++) {
                const uint32_t ao =
                    stb + ARR + (uint32_t)((wm * 64 + mt * 16) * 48) + aOff;
                uint32_t al[4];
                LDSM_X4(al[0], al[1], al[2], al[3], ao);
#pragma unroll
                for (int nt = 0; nt < 4; nt++)
                    MMA_BF16(acc[mt][nt], al, (&bh4[nt >> 1][(nt & 1) * 2]));
            }
        }
    }

    // ---------------- epilogue ----------------
    float* Cf = (EPI == 0) ? Cfg + (size_t)bz * sC : nullptr;
    bf16*  Ch = (EPI == 2) ? Chg + (size_t)bz * sC : nullptr;
    bf16*  Cl = (EPI == 2) ? Clg + (size_t)bz * sC : nullptr;

#pragma unroll
    for (int mt = 0; mt < 4; mt++) {
        const int r0 = m0 + wm * 64 + mt * 16 + g;
#pragma unroll
        for (int nt = 0; nt < 4; nt++) {
            const int col = n0 + wn * 32 + nt * 8 + tq * 2;
            const float c0 = acc[mt][nt][0], c1 = acc[mt][nt][1];
            const float c2 = acc[mt][nt][2], c3 = acc[mt][nt][3];
            if (EPI == 0) {
                *(float2*)(Cf + (size_t)r0 * N + col)       = make_float2(c0, c1);
                *(float2*)(Cf + (size_t)(r0 + 8) * N + col) = make_float2(c2, c3);
            } else {
                bf16 h0,h1,h2,h3,l0,l1,l2,l3;
                split2(c0,h0,l0); split2(c1,h1,l1); split2(c2,h2,l2); split2(c3,h3,l3);
                __nv_bfloat162 t;
                t.x=h0; t.y=h1; *(__nv_bfloat162*)(Ch + (size_t)r0*N + col)     = t;
                t.x=h2; t.y=h3; *(__nv_bfloat162*)(Ch + (size_t)(r0+8)*N + col) = t;
                t.x=l0; t.y=l1; *(__nv_bfloat162*)(Cl + (size_t)r0*N + col)     = t;
                t.x=l2; t.y=l3; *(__nv_bfloat162*)(Cl + (size_t)(r0+8)*N + col) = t;
            }
        }
    }
}

// ---------------------------------------------------------------------------
// Variable-length row softmax over compacted scores [b,t,j], j in [0, nb).
// Zero-fills pf only up to pad16(nb) -- exactly the range GEMM3 reads
// (its Klogic = pad16(nb)).
// ---------------------------------------------------------------------------
__global__ __launch_bounds__(256)
void softmax_rows(const float* __restrict__ scores, const int* __restrict__ nbp,
                  __half* __restrict__ pf)
{
    const int tid = threadIdx.x;
    const int b = blockIdx.x >> 11;         // SEQ2 = 2048 rows per batch
    const int nb = nbp[b];
    const int npad = (nb + 127) & ~127;
    const int nwrite = (nb + 15) & ~15;     // GEMM3 reads exactly pad16(nb)
    const size_t base = (size_t)blockIdx.x * SEQ1;
    const float* row = scores + base;

    float v[8];
    float mx = -3.4e38f;
#pragma unroll
    for (int i = 0; i < 8; i++) {
        const int j = tid + (i << 8);
        v[i] = (j < nb) ? row[j] : -3.4e38f;
        if (j >= npad) continue;
        mx = fmaxf(mx, v[i]);
    }
#pragma unroll
    for (int o = 16; o > 0; o >>= 1)
        mx = fmaxf(mx, __shfl_xor_sync(0xffffffffu, mx, o));

    __shared__ float smax[8];
    __shared__ float ssum[8];
    if ((tid & 31) == 0) smax[tid >> 5] = mx;
    __syncthreads();
    mx = smax[0];
#pragma unroll
    for (int w = 1; w < 8; w++) mx = fmaxf(mx, smax[w]);

    float s = 0.0f;
#pragma unroll
    for (int i = 0; i < 8; i++) {
        const int j = tid + (i << 8);
        v[i] = (j < nb) ? __expf(v[i] - mx) : 0.0f;
        s += v[i];
    }
#pragma unroll
    for (int o = 16; o > 0; o >>= 1)
        s += __shfl_xor_sync(0xffffffffu, s, o);
    if ((tid & 31) == 0) ssum[tid >> 5] = s;
    __syncthreads();
    s = ssum[0];
#pragma unroll
    for (int w = 1; w < 8; w++) s += ssum[w];

    const float inv = 1.0f / s;
#pragma unroll
    for (int i = 0; i < 8; i++) {
        const int j = tid + (i << 8);
        if (j < nwrite)
            pf[base + j] = __float2half((j < nb) ? v[i] * inv : 0.0f);
    }
}

// ---------------------------------------------------------------------------
extern "C" void kernel_launch(void* const* d_in, const int* in_sizes, int n_in,
                              void* d_out, int out_size)
{
    const float*        input1 = (const float*)d_in[0];          // [B,S1,D]
    const float*        input2 = (const float*)d_in[1];          // [B,S2,D]
    const unsigned int* mask   = (const unsigned int*)d_in[2];   // [B,S1] words
    const float*        weight = (const float*)d_in[3];          // [D,D]
    float*              out    = (float*)d_out;                  // [B,S2,D]

    bf16 *in1h,*in1l,*in2h,*in2l,*wh,*wl,*o1h,*o1l;
    __half *t1f, *pf;
    float *scoresp; int *idxp, *nbp;
    cudaGetSymbolAddress((void**)&idxp, g_idx);
    cudaGetSymbolAddress((void**)&nbp,  g_nb);
    cudaGetSymbolAddress((void**)&in1h, g_in1h);
    cudaGetSymbolAddress((void**)&in1l, g_in1l);
    cudaGetSymbolAddress((void**)&in2h, g_in2h);
    cudaGetSymbolAddress((void**)&in2l, g_in2l);
    cudaGetSymbolAddress((void**)&wh,  g_wh);
    cudaGetSymbolAddress((void**)&wl,  g_wl);
    cudaGetSymbolAddress((void**)&o1h, g_o1h);
    cudaGetSymbolAddress((void**)&o1l, g_o1l);
    cudaGetSymbolAddress((void**)&t1f, g_t1f);
    cudaGetSymbolAddress((void**)&pf,  g_pf);
    cudaGetSymbolAddress((void**)&scoresp, g_scores);

    const int SMEM3 = 98304;   // PROD=3: 4 stages x 4 arrays x 6144B
    const int SMEM1 = 49152;   // PROD=1: 4 stages x 2 arrays x 6144B
    cudaFuncSetAttribute(gemm_mma<2,1,3>, cudaFuncAttributeMaxDynamicSharedMemorySize, SMEM3);
    cudaFuncSetAttribute(gemm_mma<0,2,3>, cudaFuncAttributeMaxDynamicSharedMemorySize, SMEM3);
    cudaFuncSetAttribute(gemm_mma<0,3,1>, cudaFuncAttributeMaxDynamicSharedMemorySize, SMEM1);

    const size_t n1 = (size_t)BATCH * SEQ1 * DIM;

    // 0) mask compaction + operand prep
    build_idx<<<BATCH, 256>>>(mask, idxp, nbp);
    split_kernel<<<(unsigned)(n1 / 1024), 256>>>(input2, in2h, in2l);
    split_kernel<<<(unsigned)((size_t)DIM * DIM / 1024), 256>>>(weight, wh, wl);
    gather_split<<<dim3(SEQ1 / 32, DIM / 64, BATCH), 256>>>(
        input1, idxp, nbp, in1h, in1l, t1f);

    // 1) out1c[b,j,:] = in1c[b,j,:] @ W^T  (compacted M, split-bf16 out)
    gemm_mma<2,1,3><<<dim3(DIM / 128, SEQ1 / 128, BATCH), 256, SMEM3>>>(
        in1h, in1l, wh, wl, nullptr, o1h, o1l, nbp,
        DIM, DIM, DIM,
        (size_t)SEQ1 * DIM, 0, (size_t)SEQ1 * DIM);

    // 2) scoresT[b,t,j] = in2[b,t,:] . out1c[b,j,:]  (compacted N)
    gemm_mma<0,2,3><<<dim3(SEQ1 / 128, SEQ2 / 128, BATCH), 256, SMEM3>>>(
        in2h, in2l, o1h, o1l, scoresp, nullptr, nullptr, nbp,
        SEQ1, DIM, DIM,
        (size_t)SEQ2 * DIM, (size_t)SEQ1 * DIM, (size_t)SEQ2 * SEQ1);

    // 3) softmax over compacted j -> single fp16 P (zero-padded to pad16)
    softmax_rows<<<BATCH * SEQ2, 256>>>(scoresp, nbp, pf);

    // 4) out[b,t,d] = sum_j P[b,t,j] * in1c[b,j,d]  (compacted K, fp16 1-prod)
    gemm_mma<0,3,1><<<dim3(DIM / 128, SEQ2 / 128, BATCH), 256, SMEM1>>>(
        (const bf16*)pf, nullptr, (const bf16*)t1f, nullptr,
        out, nullptr, nullptr, nbp,
        DIM, SEQ1, SEQ1,
        (size_t)SEQ2 * SEQ1, (size_t)DIM * SEQ1, (size_t)SEQ2 * DIM);
}